// round 14
// baseline (speedup 1.0000x reference)
#include <cuda_runtime.h>
#include <math.h>

// HG2Vec fused loss, v14 = v12 decomposition + cp.async staging of shared rows.
// Warp per (position, context-half); 4 warps/CTA = 2 positions per iteration.
// Per position the two warps share t=W_out[pu] and f[0..5]=W_in[iv] (7 rows):
// those are staged 2 iterations ahead into a double-buffered SMEM tile via
// cp.async.cg — register-free structural prefetch that covers the epilogue
// bubble. Private rows (5a+5b per warp) keep v12's rotated GMEM loads.
// Port math: 14 LDS + 20 LDG = 34 rows/position through l1tex (== v12), but
// L2/GMEM requests drop 34 -> 27 and ~28 staging regs are freed:
// __launch_bounds__(128,5) -> 20 warps/SM, grid 740 persistent.
// Scattered 32-value warp reduction + butterfly, fast softplus (MUFU).
// Last-block-done deterministic reduction, ticket self-resets (graph-safe).

#define ROWBYTES  1200u
#define NPOS      16384
#define NPAIR     8192            // 2 positions per CTA iteration
#define GRID      740             // 148 SMs * 5 resident CTAs
#define THREADS   128             // 4 warps: 2 positions x 2 c-halves
#define POSBUF    8400            // 7 rows * 1200 B
#define STAGEBUF  (2 * POSBUF)    // 2 positions per stage
#define NCPY2     1050            // 14 rows * 75 16B copies

__device__ float        g_partial[GRID];
__device__ unsigned int g_ticket = 0;

#define CP_ASYNC16(DST, SRC) \
    asm volatile("cp.async.cg.shared.global [%0], [%1], 16;" :: "r"(DST), "l"(SRC) : "memory")
#define CP_COMMIT()  asm volatile("cp.async.commit_group;" ::: "memory")
#define CP_WAIT1()   asm volatile("cp.async.wait_group 1;" ::: "memory")
#define CP_WAIT0()   asm volatile("cp.async.wait_group 0;" ::: "memory")

// stage idx for PAIR Q into idx slot S: 14 ints {pos0: pu,iv0..5, pos1: ...}
#define STAGE_IDX(Q, S)                                                      \
    do {                                                                     \
        if (tid < 14) {                                                      \
            const int pq_  = ((Q) < NPAIR) ? (Q) : 0;                        \
            const int q_   = tid / 7;                                        \
            const int r_   = tid - q_ * 7;                                   \
            const int pos_ = pq_ * 2 + q_;                                   \
            idxs[S][tid] = (r_ == 0) ? pos_u[pos_]                           \
                                     : info_v[pos_ * 6 + (r_ - 1)];          \
        }                                                                    \
    } while (0)

// issue 1050 cp.async 16B copies (both positions' 7 shared rows) into stage S
#define PRODUCE(S)                                                           \
    do {                                                                     \
        const unsigned dbase_ = sbase + (unsigned)(S) * STAGEBUF;            \
        _Pragma("unroll")                                                    \
        for (int k_ = 0; k_ < 9; k_++) {                                     \
            const int n_ = tid + k_ * THREADS;                               \
            if (n_ < NCPY2) {                                                \
                const int row_ = n_ / 75;                                    \
                const int col_ = n_ - row_ * 75;                             \
                const int r_   = (row_ < 7) ? row_ : row_ - 7;               \
                const long idx_ = idxs[S][row_];                             \
                const char* src_ = ((r_ == 0) ? Wout_b : Win_b)              \
                                 + idx_ * ROWBYTES + col_ * 16;              \
                CP_ASYNC16(dbase_ + (unsigned)row_ * ROWBYTES + col_ * 16,   \
                           src_);                                            \
            }                                                                \
        }                                                                    \
    } while (0)

__global__ __launch_bounds__(THREADS, 5) void hg2vec_fused(
    const int*   __restrict__ pos_u,
    const int*   __restrict__ pos_v,
    const int*   __restrict__ info_v,
    const float* __restrict__ W_in,
    const float* __restrict__ W_out,
    const float* __restrict__ cmask,
    const float* __restrict__ sig_mask,
    const float* __restrict__ score_mask,
    float*       __restrict__ out)
{
    __shared__ __align__(16) char tile[2][STAGEBUF];
    __shared__ int   idxs[2][16];
    __shared__ float wloss[4];
    __shared__ bool  amLast;

    const int tid  = threadIdx.x;
    const int w    = tid >> 5;
    const int lane = tid & 31;
    const int grp  = w & 1;        // context half: c = grp*5 .. grp*5+4
    const int wpos = w >> 1;       // which of the 2 positions this iteration
    const unsigned sbase = (unsigned)__cvta_generic_to_shared(&tile[0][0]);

    const char* __restrict__ Win_b  = (const char*)W_in;
    const char* __restrict__ Wout_b = (const char*)W_out;

    // ---- per-lane term coefficients for the 32-value scatter ----
    float t_pre = 1.f, t_sgn = 1.f, t_wt = 1.f;
    if (lane < 2) {
        t_pre = cmask[grp * 5 + lane];
    } else {
        const int i = (lane - 2) % 6;
        t_sgn = sig_mask[i];
        t_wt  = score_mask[i];
    }
    // aux coefficients for classically-reduced sc2..4 (lanes 4..6)
    float a_pre = 0.f, a_wt = 0.f;
    if (lane >= 4 && lane < 7) {
        a_pre = cmask[grp * 5 + 2 + (lane - 4)];
        a_wt  = 1.f;
    }

    float acc_loss = 0.f;
    int pp  = blockIdx.x;
    int cur = 0;

    // ---- prime: stage+produce pairs pp (stage0) and pp+GRID (stage1) ----
    STAGE_IDX(pp,        0);
    STAGE_IDX(pp + GRID, 1);
    __syncthreads();
    PRODUCE(0); CP_COMMIT();
    PRODUCE(1); CP_COMMIT();
    STAGE_IDX(pp + 2 * GRID, 0);       // for iter0's end-of-iter produce
    STAGE_IDX(pp + 3 * GRID, 1);       // for iter1's

    // private offsets for pair pp
    unsigned pvo[5];
    {
        const int p = pp * 2 + wpos;
#pragma unroll
        for (int c = 0; c < 5; c++)
            pvo[c] = (unsigned)pos_v[p * 10 + grp * 5 + c] * ROWBYTES;
    }

    while (pp < NPAIR) {
        const int pn = pp + GRID;

        CP_WAIT1();                  // stage cur's group complete
        __syncthreads();             // tile[cur] + staged idx visible

        // ---- 35 accumulators ----
        float sc[5];
        float ai[30];
#pragma unroll
        for (int c = 0; c < 5; c++) sc[c] = 0.f;
#pragma unroll
        for (int q = 0; q < 30; q++) ai[q] = 0.f;

        const char* tf = tile[cur] + wpos * POSBUF;

        // ---- 3 d-chunks: t/f from SMEM, a/b rotated from GMEM ----
#pragma unroll
        for (int jj = 0; jj < 3; jj++) {
            const int j = lane + jj * 32;
            if (j < 75) {
                const unsigned jb = (unsigned)j * 16u;
                const float4 t4 = *(const float4*)(tf + jb);
                float4 f4[6];
#pragma unroll
                for (int i = 0; i < 6; i++)
                    f4[i] = *(const float4*)(tf + (1 + i) * ROWBYTES + jb);

                float4 ca = *(const float4*)(Win_b  + pvo[0] + jb);
                float4 cb = *(const float4*)(Wout_b + pvo[0] + jb);
#pragma unroll
                for (int c = 0; c < 5; c++) {
                    float4 na, nb;
                    if (c < 4) {
                        na = *(const float4*)(Win_b  + pvo[c + 1] + jb);
                        nb = *(const float4*)(Wout_b + pvo[c + 1] + jb);
                    }
                    sc[c] += ca.x * t4.x + ca.y * t4.y
                           + ca.z * t4.z + ca.w * t4.w;
#pragma unroll
                    for (int i = 0; i < 6; i++) {
                        ai[c * 6 + i] += cb.x * f4[i].x + cb.y * f4[i].y
                                       + cb.z * f4[i].z + cb.w * f4[i].w;
                    }
                    if (c < 4) { ca = na; cb = nb; }
                }
            }
        }

        // ---- next pair's private offsets into dead regs ----
        {
            const int pq = (pn < NPAIR) ? pn : 0;
            const int p2 = pq * 2 + wpos;
#pragma unroll
            for (int c = 0; c < 5; c++)
                pvo[c] = (unsigned)pos_v[p2 * 10 + grp * 5 + c] * ROWBYTES;
        }

        __syncthreads();             // all warps done reading tile[cur]

        // ---- refill stage cur with pair pp+2*GRID (consumed in 2 iters;
        //      in flight across the epilogue + all of next iteration) ----
        if (pp + 2 * GRID < NPAIR) { PRODUCE(cur); }
        CP_COMMIT();                 // uniform group accounting
        STAGE_IDX(pp + 4 * GRID, cur);

        // ---- scattered 32-value warp reduction ----
        {
            float v0[16];
            {
                float a, b;
                a = sc[0]  + __shfl_xor_sync(0xffffffffu, sc[0],  16);
                b = ai[14] + __shfl_xor_sync(0xffffffffu, ai[14], 16);
                v0[0] = (lane & 16) ? b : a;
                a = sc[1]  + __shfl_xor_sync(0xffffffffu, sc[1],  16);
                b = ai[15] + __shfl_xor_sync(0xffffffffu, ai[15], 16);
                v0[1] = (lane & 16) ? b : a;
#pragma unroll
                for (int q = 2; q < 16; q++) {
                    a = ai[q - 2]  + __shfl_xor_sync(0xffffffffu, ai[q - 2],  16);
                    b = ai[q + 14] + __shfl_xor_sync(0xffffffffu, ai[q + 14], 16);
                    v0[q] = (lane & 16) ? b : a;
                }
            }
            float v1[8];
#pragma unroll
            for (int q = 0; q < 8; q++) {
                const float a = v0[q]     + __shfl_xor_sync(0xffffffffu, v0[q],     8);
                const float b = v0[q + 8] + __shfl_xor_sync(0xffffffffu, v0[q + 8], 8);
                v1[q] = (lane & 8) ? b : a;
            }
            float v2[4];
#pragma unroll
            for (int q = 0; q < 4; q++) {
                const float a = v1[q]     + __shfl_xor_sync(0xffffffffu, v1[q],     4);
                const float b = v1[q + 4] + __shfl_xor_sync(0xffffffffu, v1[q + 4], 4);
                v2[q] = (lane & 4) ? b : a;
            }
            float v3[2];
#pragma unroll
            for (int q = 0; q < 2; q++) {
                const float a = v2[q]     + __shfl_xor_sync(0xffffffffu, v2[q],     2);
                const float b = v2[q + 2] + __shfl_xor_sync(0xffffffffu, v2[q + 2], 2);
                v3[q] = (lane & 2) ? b : a;
            }
            float v4;
            {
                const float a = v3[0] + __shfl_xor_sync(0xffffffffu, v3[0], 1);
                const float b = v3[1] + __shfl_xor_sync(0xffffffffu, v3[1], 1);
                v4 = (lane & 1) ? b : a;
            }

            // classic butterfly for the 3 remaining score sums
#pragma unroll
            for (int off = 16; off; off >>= 1) {
                sc[2] += __shfl_xor_sync(0xffffffffu, sc[2], off);
                sc[3] += __shfl_xor_sync(0xffffffffu, sc[3], off);
                sc[4] += __shfl_xor_sync(0xffffffffu, sc[4], off);
            }

            // ---- lane-parallel loss terms ----
            const float x = fminf(fmaxf(v4 * t_pre, -10.f), 10.f) * t_sgn;
            acc_loss += __logf(1.f + __expf(-x)) * t_wt;

            const float sa = (lane == 4) ? sc[2] : ((lane == 5) ? sc[3] : sc[4]);
            const float xa = fminf(fmaxf(sa * a_pre, -10.f), 10.f);
            acc_loss += __logf(1.f + __expf(-xa)) * a_wt;
        }

        cur ^= 1;
        pp = pn;
    }

    CP_WAIT0();                      // drain outstanding copies before exit path

    // ---- block reduction ----
#pragma unroll
    for (int off = 16; off; off >>= 1)
        acc_loss += __shfl_xor_sync(0xffffffffu, acc_loss, off);
    if (lane == 0) wloss[w] = acc_loss;
    __syncthreads();

    if (tid == 0) {
        float s = wloss[0] + wloss[1] + wloss[2] + wloss[3];
        g_partial[blockIdx.x] = s;
        __threadfence();
        unsigned t = atomicAdd(&g_ticket, 1u);
        amLast = (t == GRID - 1);
    }
    __syncthreads();

    // ---- last block: deterministic fixed-order final sum ----
    if (amLast) {
        __shared__ float fs[THREADS];
        float v = 0.f;
        for (int i = tid; i < GRID; i += THREADS)
            v += __ldcg(&g_partial[i]);
        fs[tid] = v;
        __syncthreads();
#pragma unroll
        for (int st = THREADS / 2; st; st >>= 1) {
            if (tid < st) fs[tid] += fs[tid + st];
            __syncthreads();
        }
        if (tid == 0) {
            out[0] = fs[0];
            g_ticket = 0;            // reset for next graph replay
            __threadfence();
        }
    }
}

extern "C" void kernel_launch(void* const* d_in, const int* in_sizes, int n_in,
                              void* d_out, int out_size)
{
    const int*   pos_u  = (const int*)  d_in[0];
    const int*   pos_v  = (const int*)  d_in[1];
    const int*   info_v = (const int*)  d_in[2];
    const float* W_in   = (const float*)d_in[3];
    const float* W_out  = (const float*)d_in[4];
    const float* cmask  = (const float*)d_in[5];
    const float* sigm   = (const float*)d_in[6];
    const float* smask  = (const float*)d_in[7];

    hg2vec_fused<<<GRID, THREADS>>>(pos_u, pos_v, info_v, W_in, W_out,
                                    cmask, sigm, smask, (float*)d_out);
}

// round 16
// speedup vs baseline: 1.0971x; 1.0971x over previous
#include <cuda_runtime.h>
#include <math.h>

// HG2Vec fused loss, v16 = v12 + next-position t/f chunk0 preload.
// Warp per (position, context-half): 35 dots, 17 rows read once per warp.
//  - t4/f4 (the 7 shared rows' chunk) are persistent registers; after the
//    next pair's indices land in the dead offset regs, the next position's
//    t/f chunk0 (7 DRAM loads, 35% of position bytes) is issued BEFORE the
//    ~92-op reduction epilogue, so memory stays in flight through it.
//  - a/b pair rotation (load c+1 before FMAs of c) as in v12
//  - scattered 32-value warp reduction + butterfly for sc2..4 (v12 epilogue;
//    redux.f32 does not exist on sm_103 — confirmed by ptxas in R15)
//  - __launch_bounds__(128,4): 16 warps/SM, grid 592 persistent
//  - last-block-done deterministic reduction, ticket self-resets (graph-safe)

#define ROWBYTES  1200u
#define NPOS      16384
#define NPAIR     8192            // 2 positions per CTA iteration
#define GRID      592             // 148 SMs * 4 resident CTAs
#define THREADS   128             // 4 warps: 2 positions x 2 c-halves

__device__ float        g_partial[GRID];
__device__ unsigned int g_ticket = 0;

// load t + f[0..5] chunk at byte offset JB (uses current puo/ivo)
#define TF_LOAD(JB)                                                          \
    do {                                                                     \
        t4 = *(const float4*)(Wout_b + puo + (JB));                          \
        _Pragma("unroll")                                                    \
        for (int i_ = 0; i_ < 6; i_++)                                       \
            f4[i_] = *(const float4*)(Win_b + ivo[i_] + (JB));               \
    } while (0)

// accumulate one chunk at JB: a/b rotated from GMEM, t/f from registers
#define CHUNK_BODY(JB)                                                       \
    do {                                                                     \
        float4 ca = *(const float4*)(Win_b  + pvo[0] + (JB));                \
        float4 cb = *(const float4*)(Wout_b + pvo[0] + (JB));                \
        _Pragma("unroll")                                                    \
        for (int c_ = 0; c_ < 5; c_++) {                                     \
            float4 na, nb;                                                   \
            if (c_ < 4) {                                                    \
                na = *(const float4*)(Win_b  + pvo[c_ + 1] + (JB));          \
                nb = *(const float4*)(Wout_b + pvo[c_ + 1] + (JB));          \
            }                                                                \
            sc[c_] += ca.x * t4.x + ca.y * t4.y                              \
                    + ca.z * t4.z + ca.w * t4.w;                             \
            _Pragma("unroll")                                                \
            for (int i_ = 0; i_ < 6; i_++) {                                 \
                ai[c_ * 6 + i_] += cb.x * f4[i_].x + cb.y * f4[i_].y         \
                                 + cb.z * f4[i_].z + cb.w * f4[i_].w;        \
            }                                                                \
            if (c_ < 4) { ca = na; cb = nb; }                                \
        }                                                                    \
    } while (0)

__global__ __launch_bounds__(THREADS, 4) void hg2vec_fused(
    const int*   __restrict__ pos_u,
    const int*   __restrict__ pos_v,
    const int*   __restrict__ info_v,
    const float* __restrict__ W_in,
    const float* __restrict__ W_out,
    const float* __restrict__ cmask,
    const float* __restrict__ sig_mask,
    const float* __restrict__ score_mask,
    float*       __restrict__ out)
{
    __shared__ float wloss[4];
    __shared__ bool  amLast;

    const int tid  = threadIdx.x;
    const int w    = tid >> 5;
    const int lane = tid & 31;
    const int grp  = w & 1;        // context half: c = grp*5 .. grp*5+4
    const int wpos = w >> 1;       // which of the 2 positions this iteration

    const char* __restrict__ Win_b  = (const char*)W_in;
    const char* __restrict__ Wout_b = (const char*)W_out;

    // ---- per-lane term coefficients for the 32-value scatter ----
    // lane 0,1 -> score c = grp*5 + lane ; lane 2..31 -> info k = lane-2
    float t_pre = 1.f, t_sgn = 1.f, t_wt = 1.f;
    if (lane < 2) {
        t_pre = cmask[grp * 5 + lane];
    } else {
        const int i = (lane - 2) % 6;
        t_sgn = sig_mask[i];
        t_wt  = score_mask[i];
    }
    // aux coefficients for classically-reduced sc2..4 (lanes 4..6)
    float a_pre = 0.f, a_wt = 0.f;
    if (lane >= 4 && lane < 7) {
        a_pre = cmask[grp * 5 + 2 + (lane - 4)];
        a_wt  = 1.f;
    }

    const unsigned jb0 = (unsigned)lane * 16u;
    const unsigned jb1 = jb0 + 512u;
    const unsigned jb2 = jb0 + 1024u;   // lanes 0..10 only

    float acc_loss = 0.f;
    int pp = blockIdx.x;

    // ---- prime: offsets for first pair + t/f chunk0 preload ----
    unsigned puo;
    unsigned pvo[5], ivo[6];
    {
        const int p = pp * 2 + wpos;
        puo = (unsigned)pos_u[p] * ROWBYTES;
#pragma unroll
        for (int c = 0; c < 5; c++)
            pvo[c] = (unsigned)pos_v[p * 10 + grp * 5 + c] * ROWBYTES;
#pragma unroll
        for (int i = 0; i < 6; i++)
            ivo[i] = (unsigned)info_v[p * 6 + i] * ROWBYTES;
    }
    float4 t4, f4[6];
    TF_LOAD(jb0);

    while (pp < NPAIR) {
        const int pn = pp + GRID;

        // ---- 35 accumulators ----
        float sc[5];
        float ai[30];
#pragma unroll
        for (int c = 0; c < 5; c++) sc[c] = 0.f;
#pragma unroll
        for (int q = 0; q < 30; q++) ai[q] = 0.f;

        // chunk 0: t/f preloaded
        CHUNK_BODY(jb0);
        // chunk 1
        TF_LOAD(jb1);
        CHUNK_BODY(jb1);
        // chunk 2 (lanes 0..10)
        if (lane < 11) {
            TF_LOAD(jb2);
            CHUNK_BODY(jb2);
        }

        // ---- next pair's indices into (now dead) offset regs ----
        {
            const int pq = (pn < NPAIR) ? pn : 0;
            const int p2 = pq * 2 + wpos;
            puo = (unsigned)pos_u[p2] * ROWBYTES;
#pragma unroll
            for (int c = 0; c < 5; c++)
                pvo[c] = (unsigned)pos_v[p2 * 10 + grp * 5 + c] * ROWBYTES;
#pragma unroll
            for (int i = 0; i < 6; i++)
                ivo[i] = (unsigned)info_v[p2 * 6 + i] * ROWBYTES;
        }

        // ---- preload next position's t/f chunk0: 7 DRAM loads in flight
        //      across the reduction epilogue below ----
        TF_LOAD(jb0);

        // ---- scattered 32-value warp reduction (v12 epilogue) ----
        // x[0..31] = {sc0, sc1, ai[0..29]}; lane L ends with sum of value L.
        {
            float v0[16];
            {
                float a, b;
                a = sc[0]  + __shfl_xor_sync(0xffffffffu, sc[0],  16);
                b = ai[14] + __shfl_xor_sync(0xffffffffu, ai[14], 16);
                v0[0] = (lane & 16) ? b : a;
                a = sc[1]  + __shfl_xor_sync(0xffffffffu, sc[1],  16);
                b = ai[15] + __shfl_xor_sync(0xffffffffu, ai[15], 16);
                v0[1] = (lane & 16) ? b : a;
#pragma unroll
                for (int q = 2; q < 16; q++) {
                    a = ai[q - 2]  + __shfl_xor_sync(0xffffffffu, ai[q - 2],  16);
                    b = ai[q + 14] + __shfl_xor_sync(0xffffffffu, ai[q + 14], 16);
                    v0[q] = (lane & 16) ? b : a;
                }
            }
            float v1[8];
#pragma unroll
            for (int q = 0; q < 8; q++) {
                const float a = v0[q]     + __shfl_xor_sync(0xffffffffu, v0[q],     8);
                const float b = v0[q + 8] + __shfl_xor_sync(0xffffffffu, v0[q + 8], 8);
                v1[q] = (lane & 8) ? b : a;
            }
            float v2[4];
#pragma unroll
            for (int q = 0; q < 4; q++) {
                const float a = v1[q]     + __shfl_xor_sync(0xffffffffu, v1[q],     4);
                const float b = v1[q + 4] + __shfl_xor_sync(0xffffffffu, v1[q + 4], 4);
                v2[q] = (lane & 4) ? b : a;
            }
            float v3[2];
#pragma unroll
            for (int q = 0; q < 2; q++) {
                const float a = v2[q]     + __shfl_xor_sync(0xffffffffu, v2[q],     2);
                const float b = v2[q + 2] + __shfl_xor_sync(0xffffffffu, v2[q + 2], 2);
                v3[q] = (lane & 2) ? b : a;
            }
            float v4;
            {
                const float a = v3[0] + __shfl_xor_sync(0xffffffffu, v3[0], 1);
                const float b = v3[1] + __shfl_xor_sync(0xffffffffu, v3[1], 1);
                v4 = (lane & 1) ? b : a;
            }

            // classic butterfly for the 3 remaining score sums
#pragma unroll
            for (int off = 16; off; off >>= 1) {
                sc[2] += __shfl_xor_sync(0xffffffffu, sc[2], off);
                sc[3] += __shfl_xor_sync(0xffffffffu, sc[3], off);
                sc[4] += __shfl_xor_sync(0xffffffffu, sc[4], off);
            }

            // ---- lane-parallel loss terms ----
            const float x = fminf(fmaxf(v4 * t_pre, -10.f), 10.f) * t_sgn;
            acc_loss += __logf(1.f + __expf(-x)) * t_wt;

            const float sa = (lane == 4) ? sc[2] : ((lane == 5) ? sc[3] : sc[4]);
            const float xa = fminf(fmaxf(sa * a_pre, -10.f), 10.f);
            acc_loss += __logf(1.f + __expf(-xa)) * a_wt;
        }

        pp = pn;
    }

    // ---- block reduction ----
#pragma unroll
    for (int off = 16; off; off >>= 1)
        acc_loss += __shfl_xor_sync(0xffffffffu, acc_loss, off);
    if (lane == 0) wloss[w] = acc_loss;
    __syncthreads();

    if (tid == 0) {
        float s = wloss[0] + wloss[1] + wloss[2] + wloss[3];
        g_partial[blockIdx.x] = s;
        __threadfence();
        unsigned t = atomicAdd(&g_ticket, 1u);
        amLast = (t == GRID - 1);
    }
    __syncthreads();

    // ---- last block: deterministic fixed-order final sum ----
    if (amLast) {
        __shared__ float fs[THREADS];
        float v = 0.f;
        for (int i = tid; i < GRID; i += THREADS)
            v += __ldcg(&g_partial[i]);
        fs[tid] = v;
        __syncthreads();
#pragma unroll
        for (int st = THREADS / 2; st; st >>= 1) {
            if (tid < st) fs[tid] += fs[tid + st];
            __syncthreads();
        }
        if (tid == 0) {
            out[0] = fs[0];
            g_ticket = 0;            // reset for next graph replay
            __threadfence();
        }
    }
}

extern "C" void kernel_launch(void* const* d_in, const int* in_sizes, int n_in,
                              void* d_out, int out_size)
{
    const int*   pos_u  = (const int*)  d_in[0];
    const int*   pos_v  = (const int*)  d_in[1];
    const int*   info_v = (const int*)  d_in[2];
    const float* W_in   = (const float*)d_in[3];
    const float* W_out  = (const float*)d_in[4];
    const float* cmask  = (const float*)d_in[5];
    const float* sigm   = (const float*)d_in[6];
    const float* smask  = (const float*)d_in[7];

    hg2vec_fused<<<GRID, THREADS>>>(pos_u, pos_v, info_v, W_in, W_out,
                                    cmask, sigm, smask, (float*)d_out);
}

// round 17
// speedup vs baseline: 1.1883x; 1.0831x over previous
#include <cuda_runtime.h>
#include <math.h>

// HG2Vec fused loss, v17 = v12 + L2-residency policy for W_in.
// v12 profile showed L2 hit ~28% (381MB DRAM vs 531MB requests): both 120MB
// tables thrash the 126MB L2. W_in carries 59% of row-reads (10 ctx_in +
// 6 info_in of 27 rows/position) and alone FITS L2. All W_in loads are issued
// with createpolicy.fractional.L2::evict_last + ld.global.L2::cache_hint so
// W_in becomes L2-resident (persists across graph replays too); W_out streams.
// Expected DRAM traffic 381 -> ~220MB on the binding pipe.
// Everything else is byte-for-byte v12 (best: 78.0us): warp per (position,
// c-half), 35 accumulators, 17 rows once per warp, a/b rotation, scattered
// 32-value warp reduction + butterfly, fast softplus, __launch_bounds__(128,4),
// grid 592 persistent, last-block-done deterministic reduction.

#define ROWBYTES  1200u
#define NPOS      16384
#define NPAIR     8192            // 2 positions per CTA iteration
#define GRID      592             // 148 SMs * 4 resident CTAs
#define THREADS   128             // 4 warps: 2 positions x 2 c-halves

__device__ float        g_partial[GRID];
__device__ unsigned int g_ticket = 0;

// float4 global load with an L2 eviction-policy hint (W_in -> evict_last)
__device__ __forceinline__ float4 ldg_pol(const char* p, unsigned long long pol)
{
    float4 r;
    asm("ld.global.L2::cache_hint.v4.f32 {%0,%1,%2,%3}, [%4], %5;"
        : "=f"(r.x), "=f"(r.y), "=f"(r.z), "=f"(r.w)
        : "l"(p), "l"(pol));
    return r;
}

__global__ __launch_bounds__(THREADS, 4) void hg2vec_fused(
    const int*   __restrict__ pos_u,
    const int*   __restrict__ pos_v,
    const int*   __restrict__ info_v,
    const float* __restrict__ W_in,
    const float* __restrict__ W_out,
    const float* __restrict__ cmask,
    const float* __restrict__ sig_mask,
    const float* __restrict__ score_mask,
    float*       __restrict__ out)
{
    __shared__ float wloss[4];
    __shared__ bool  amLast;

    const int tid  = threadIdx.x;
    const int w    = tid >> 5;
    const int lane = tid & 31;
    const int grp  = w & 1;        // context half: c = grp*5 .. grp*5+4
    const int wpos = w >> 1;       // which of the 2 positions this iteration

    const char* __restrict__ Win_b  = (const char*)W_in;
    const char* __restrict__ Wout_b = (const char*)W_out;

    // L2 policy: W_in lines are evict_last (W_in ~120MB fits the 126MB L2)
    unsigned long long pol;
    asm("createpolicy.fractional.L2::evict_last.b64 %0, 1.0;" : "=l"(pol));

    // ---- per-lane term coefficients for the 32-value scatter ----
    // lane 0,1 -> score c = grp*5 + lane ; lane 2..31 -> info k = lane-2
    float t_pre = 1.f, t_sgn = 1.f, t_wt = 1.f;
    if (lane < 2) {
        t_pre = cmask[grp * 5 + lane];
    } else {
        const int i = (lane - 2) % 6;
        t_sgn = sig_mask[i];
        t_wt  = score_mask[i];
    }
    // aux coefficients for classically-reduced sc2..4 (lanes 4..6)
    float a_pre = 0.f, a_wt = 0.f;
    if (lane >= 4 && lane < 7) {
        a_pre = cmask[grp * 5 + 2 + (lane - 4)];
        a_wt  = 1.f;
    }

    float acc_loss = 0.f;

    int pp = blockIdx.x;

    // ---- prime offsets for the first position ----
    unsigned puo;
    unsigned pvo[5], ivo[6];
    {
        const int p = pp * 2 + wpos;
        puo = (unsigned)pos_u[p] * ROWBYTES;
#pragma unroll
        for (int c = 0; c < 5; c++)
            pvo[c] = (unsigned)pos_v[p * 10 + grp * 5 + c] * ROWBYTES;
#pragma unroll
        for (int i = 0; i < 6; i++)
            ivo[i] = (unsigned)info_v[p * 6 + i] * ROWBYTES;
    }

    while (pp < NPAIR) {
        const int pn = pp + GRID;

        // ---- 35 accumulators ----
        float sc[5];
        float ai[30];
#pragma unroll
        for (int c = 0; c < 5; c++) sc[c] = 0.f;
#pragma unroll
        for (int q = 0; q < 30; q++) ai[q] = 0.f;

        // ---- 3 d-chunks; each row read once by this warp ----
#pragma unroll
        for (int jj = 0; jj < 3; jj++) {
            const int j = lane + jj * 32;
            if (j < 75) {
                const unsigned jb = (unsigned)j * 16u;
                const float4 t4 = *(const float4*)(Wout_b + puo + jb);
                float4 f4[6];
#pragma unroll
                for (int i = 0; i < 6; i++)
                    f4[i] = ldg_pol(Win_b + ivo[i] + jb, pol);   // W_in resident

                // a/b pair rotation: load c+1 before consuming c
                float4 ca = ldg_pol(Win_b + pvo[0] + jb, pol);   // W_in resident
                float4 cb = *(const float4*)(Wout_b + pvo[0] + jb);
#pragma unroll
                for (int c = 0; c < 5; c++) {
                    float4 na, nb;
                    if (c < 4) {
                        na = ldg_pol(Win_b + pvo[c + 1] + jb, pol);
                        nb = *(const float4*)(Wout_b + pvo[c + 1] + jb);
                    }
                    sc[c] += ca.x * t4.x + ca.y * t4.y
                           + ca.z * t4.z + ca.w * t4.w;
#pragma unroll
                    for (int i = 0; i < 6; i++) {
                        ai[c * 6 + i] += cb.x * f4[i].x + cb.y * f4[i].y
                                       + cb.z * f4[i].z + cb.w * f4[i].w;
                    }
                    if (c < 4) { ca = na; cb = nb; }
                }
            }
        }

        // ---- offsets dead: load next iteration's indices now ----
        {
            const int pq = (pn < NPAIR) ? pn : 0;
            const int p2 = pq * 2 + wpos;
            puo = (unsigned)pos_u[p2] * ROWBYTES;
#pragma unroll
            for (int c = 0; c < 5; c++)
                pvo[c] = (unsigned)pos_v[p2 * 10 + grp * 5 + c] * ROWBYTES;
#pragma unroll
            for (int i = 0; i < 6; i++)
                ivo[i] = (unsigned)info_v[p2 * 6 + i] * ROWBYTES;
        }

        // ---- scattered 32-value warp reduction ----
        // x[0..31] = {sc0, sc1, ai[0..29]}; lane L ends with sum of value L.
        {
            float v0[16];
            {
                float a, b;
                a = sc[0]  + __shfl_xor_sync(0xffffffffu, sc[0],  16);
                b = ai[14] + __shfl_xor_sync(0xffffffffu, ai[14], 16);
                v0[0] = (lane & 16) ? b : a;
                a = sc[1]  + __shfl_xor_sync(0xffffffffu, sc[1],  16);
                b = ai[15] + __shfl_xor_sync(0xffffffffu, ai[15], 16);
                v0[1] = (lane & 16) ? b : a;
#pragma unroll
                for (int q = 2; q < 16; q++) {
                    a = ai[q - 2]  + __shfl_xor_sync(0xffffffffu, ai[q - 2],  16);
                    b = ai[q + 14] + __shfl_xor_sync(0xffffffffu, ai[q + 14], 16);
                    v0[q] = (lane & 16) ? b : a;
                }
            }
            float v1[8];
#pragma unroll
            for (int q = 0; q < 8; q++) {
                const float a = v0[q]     + __shfl_xor_sync(0xffffffffu, v0[q],     8);
                const float b = v0[q + 8] + __shfl_xor_sync(0xffffffffu, v0[q + 8], 8);
                v1[q] = (lane & 8) ? b : a;
            }
            float v2[4];
#pragma unroll
            for (int q = 0; q < 4; q++) {
                const float a = v1[q]     + __shfl_xor_sync(0xffffffffu, v1[q],     4);
                const float b = v1[q + 4] + __shfl_xor_sync(0xffffffffu, v1[q + 4], 4);
                v2[q] = (lane & 4) ? b : a;
            }
            float v3[2];
#pragma unroll
            for (int q = 0; q < 2; q++) {
                const float a = v2[q]     + __shfl_xor_sync(0xffffffffu, v2[q],     2);
                const float b = v2[q + 2] + __shfl_xor_sync(0xffffffffu, v2[q + 2], 2);
                v3[q] = (lane & 2) ? b : a;
            }
            float v4;
            {
                const float a = v3[0] + __shfl_xor_sync(0xffffffffu, v3[0], 1);
                const float b = v3[1] + __shfl_xor_sync(0xffffffffu, v3[1], 1);
                v4 = (lane & 1) ? b : a;
            }

            // classic butterfly for the 3 remaining score sums
#pragma unroll
            for (int off = 16; off; off >>= 1) {
                sc[2] += __shfl_xor_sync(0xffffffffu, sc[2], off);
                sc[3] += __shfl_xor_sync(0xffffffffu, sc[3], off);
                sc[4] += __shfl_xor_sync(0xffffffffu, sc[4], off);
            }

            // ---- lane-parallel loss terms ----
            const float x = fminf(fmaxf(v4 * t_pre, -10.f), 10.f) * t_sgn;
            acc_loss += __logf(1.f + __expf(-x)) * t_wt;

            const float sa = (lane == 4) ? sc[2] : ((lane == 5) ? sc[3] : sc[4]);
            const float xa = fminf(fmaxf(sa * a_pre, -10.f), 10.f);
            acc_loss += __logf(1.f + __expf(-xa)) * a_wt;
        }

        pp = pn;
    }

    // ---- block reduction ----
#pragma unroll
    for (int off = 16; off; off >>= 1)
        acc_loss += __shfl_xor_sync(0xffffffffu, acc_loss, off);
    if (lane == 0) wloss[w] = acc_loss;
    __syncthreads();

    if (tid == 0) {
        float s = wloss[0] + wloss[1] + wloss[2] + wloss[3];
        g_partial[blockIdx.x] = s;
        __threadfence();
        unsigned t = atomicAdd(&g_ticket, 1u);
        amLast = (t == GRID - 1);
    }
    __syncthreads();

    // ---- last block: deterministic fixed-order final sum ----
    if (amLast) {
        __shared__ float fs[THREADS];
        float v = 0.f;
        for (int i = tid; i < GRID; i += THREADS)
            v += __ldcg(&g_partial[i]);
        fs[tid] = v;
        __syncthreads();
#pragma unroll
        for (int st = THREADS / 2; st; st >>= 1) {
            if (tid < st) fs[tid] += fs[tid + st];
            __syncthreads();
        }
        if (tid == 0) {
            out[0] = fs[0];
            g_ticket = 0;            // reset for next graph replay
            __threadfence();
        }
    }
}

extern "C" void kernel_launch(void* const* d_in, const int* in_sizes, int n_in,
                              void* d_out, int out_size)
{
    const int*   pos_u  = (const int*)  d_in[0];
    const int*   pos_v  = (const int*)  d_in[1];
    const int*   info_v = (const int*)  d_in[2];
    const float* W_in   = (const float*)d_in[3];
    const float* W_out  = (const float*)d_in[4];
    const float* cmask  = (const float*)d_in[5];
    const float* sigm   = (const float*)d_in[6];
    const float* smask  = (const float*)d_in[7];

    hg2vec_fused<<<GRID, THREADS>>>(pos_u, pos_v, info_v, W_in, W_out,
                                    cmask, sigm, smask, (float*)d_out);
}